// round 10
// baseline (speedup 1.0000x reference)
#include <cuda_runtime.h>

#define BB 64
#define TT 1024
#define NN 48
#define CH 2
#define PF 3   // 1023 steps = 341 * 3 exactly -> no tail guard, branch-free body
#define NBLK (BB + BB * CH)   // 64 chains + 128 scores = 192 blocks

#define ESTR 68                 // E column stride in floats (272B, 16B-aligned, conflict-safe)
#define EMAT (NN * ESTR)        // 3264 floats per transition matrix

// Packed f32x2 helpers (sm_100a): operate on register pairs, exact fp32 semantics.
__device__ __forceinline__ unsigned long long f2_add(unsigned long long a, unsigned long long b) {
    unsigned long long r;
    asm("add.rn.f32x2 %0, %1, %2;" : "=l"(r) : "l"(a), "l"(b));
    return r;
}
__device__ __forceinline__ unsigned long long f2_mul(unsigned long long a, unsigned long long b) {
    unsigned long long r;
    asm("mul.rn.f32x2 %0, %1, %2;" : "=l"(r) : "l"(a), "l"(b));
    return r;
}
__device__ __forceinline__ unsigned long long f2_fma(unsigned long long a, unsigned long long b,
                                                     unsigned long long c) {
    unsigned long long r;
    asm("fma.rn.f32x2 %0, %1, %2, %3;" : "=l"(r) : "l"(a), "l"(b), "l"(c));
    return r;
}
__device__ __forceinline__ float f2_hadd(unsigned long long a) {
    float lo, hi;
    asm("mov.b64 {%0, %1}, %2;" : "=f"(lo), "=f"(hi) : "l"(a));
    return lo + hi;
}

// Scratch (no cudaMalloc allowed)
__device__ float g_lognorm[BB];
__device__ float g_part[BB][CH];
__device__ int   g_count = 0;   // combine ticket; reset by combiner each call

__global__ __launch_bounds__(96) void crf_main(
    const float* __restrict__ y_true,
    const float* __restrict__ y_pred,
    const int*   __restrict__ spk,
    const float* __restrict__ tr0,
    const float* __restrict__ tr1,
    const float* __restrict__ tr2,
    float* __restrict__ out)
{
    // Chain: Ec (3 matrices, COLUMN-major, stride ESTR) + vsh[2][2][48].
    // Scores overlay the same buffer.
    __shared__ __align__(16) float sbuf[3 * EMAT + 192];
    __shared__ int s_last;
    const int tid = threadIdx.x;
    const int p = tid & 1;        // i-half: 0 -> rows 0..23, 1 -> rows 24..47
    const int j = tid >> 1;       // output column 0..47

    if (blockIdx.x < BB) {
        // ================= Forward recursion: one block per batch =================
        const int b = blockIdx.x;
        float* Ec  = sbuf;                 // exp(TRANS)^T: [k][j][i], i contiguous
        float* vsh = sbuf + 3 * EMAT;      // [buf][part][48]

        for (int idx = tid; idx < 3 * NN * NN; idx += 96) {
            int k  = idx / (NN * NN);
            int rc = idx - k * (NN * NN);
            int i  = rc / NN;
            int cj = rc - i * NN;
            const float* Tk = (k == 0) ? tr0 : (k == 1) ? tr1 : tr2;
            Ec[k * EMAT + cj * ESTR + i] = __expf(Tk[rc]);
        }

        const float* ypb = y_pred + b * TT * NN;
        const int*   spb = spk + b * (TT - 1);

        // v_0 = exp(state_0) in A-partials, zeros in B-partials.
        if (tid < 48) {
            vsh[tid]      = __expf(ypb[tid]);
            vsh[48 + tid] = 0.f;
        }

        // Register prefetch ring for emissions + transition selectors.
        float ebuf[PF];
        int   kbuf[PF];
        #pragma unroll
        for (int u = 0; u < PF; u++) {
            ebuf[u] = ypb[(1 + u) * NN + j];
            kbuf[u] = spb[u];
        }
        __syncthreads();

        float m = 0.f;
        float prod = 1.f;                  // lazy renorm-log accumulator (flushed per blk)
        int cur = 0;
        int t = 1;
        for (int blk = 0; blk < (TT - 1) / PF; blk++) {   // 341 iterations, no tail
            #pragma unroll
            for (int u = 0; u < PF; u++) {
                const int   kk   = kbuf[u];
                const float emit = ebuf[u];
                // Prefetch PF steps ahead (branch-free clamp).
                int tpc  = min(t + PF, TT - 1);
                int sidx = min(t + PF - 1, TT - 2);
                ebuf[u] = ypb[tpc * NN + j];
                kbuf[u] = spb[sidx];

                const float* A = vsh + cur * 96 + 24 * p;   // this thread's A-half slice
                const float* Bv = A + 48;                   // matching B-partial slice
                const float* base = vsh + cur * 96;

                // Renorm factor: broadcast scalars + MUFU, parallel with the dot.
                float v00 = base[0] + base[48];
                float pe  = __expf(emit);
                float rp  = __fdividef(pe, v00);

                // Pointer-select transition column (no branch), i-contiguous.
                const float* Ekj = Ec + kk * EMAT + j * ESTR + 24 * p;

                // Packed dot: 6 float4-groups; per group 2 ADD2 (A+B combine),
                // 1 MUL2 + 1 FMA2 into a per-group accumulator pair.
                unsigned long long acc[6];
                #pragma unroll
                for (int q = 0; q < 6; q++) {
                    ulonglong2 a2 = *(const ulonglong2*)(A   + 4 * q);
                    ulonglong2 b2 = *(const ulonglong2*)(Bv  + 4 * q);
                    ulonglong2 e2 = *(const ulonglong2*)(Ekj + 4 * q);
                    unsigned long long s0 = f2_add(a2.x, b2.x);
                    unsigned long long s1 = f2_add(a2.y, b2.y);
                    acc[q] = f2_fma(s1, e2.y, f2_mul(s0, e2.x));
                }
                unsigned long long t0 = f2_add(acc[0], acc[1]);
                unsigned long long t1 = f2_add(acc[2], acc[3]);
                unsigned long long t2 = f2_add(acc[4], acc[5]);
                float dot = f2_hadd(f2_add(f2_add(t0, t1), t2));

                // Store this half's partial of the next state (no shfl, no combine).
                vsh[(cur ^ 1) * 96 + p * 48 + j] = dot * rp;
                if (tid == 0) {
                    prod *= v00;                   // lazy: flush log once per blk
                    if (u == PF - 1) { m += __logf(prod); prod = 1.f; }
                }
                __syncthreads();
                cur ^= 1;
                t++;
            }
        }
        if (tid == 0) {
            const float* A = vsh + cur * 96;
            float ssum = 0.f;
            for (int q = 0; q < 48; q++) ssum += A[q] + A[48 + q];  // fixed order
            g_lognorm[b] = m + __logf(ssum);
        }
    } else {
        // ================= Score reductions: (b, chunk) blocks =================
        int idx = blockIdx.x - BB;
        int b   = idx / CH;
        int c   = idx - b * CH;

        float* l1sh = sbuf;        // [2][48] double buffer
        float* red  = sbuf + 96;   // 96-wide reduction scratch

        // Per-thread register copies of raw TRANS: column j, rows 24p..24p+23.
        float T0[24], T1[24], T2[24];
        #pragma unroll
        for (int i = 0; i < 24; i++) {
            int rc = (24 * p + i) * NN + j;
            T0[i] = tr0[rc];
            T1[i] = tr1[rc];
            T2[i] = tr2[rc];
        }

        const float* ytb = y_true + b * TT * NN;
        const float* ypb = y_pred + b * TT * NN;
        const int*   spb = spk + b * (TT - 1);

        const int LEN = (TT - 1 + CH - 1) / CH;   // 512
        int tA  = c * LEN;
        int tBn = tA + LEN; if (tBn > TT - 1) tBn = TT - 1;

        float pacc = 0.f, tacc = 0.f;

        // Software-pipelined loads (one t ahead).
        float l1 = ytb[tA * NN + j];
        float l2 = ytb[(tA + 1) * NN + j];
        float yp = ypb[tA * NN + j];
        int   kk = spb[tA];

        for (int t2 = tA; t2 < tBn; t2++) {
            if (p == 0) l1sh[(t2 & 1) * 48 + j] = l1;

            int tn = min(t2 + 1, tBn - 1);
            float l1n = ytb[tn * NN + j];
            float l2n = ytb[(tn + 1) * NN + j];
            float ypn = ypb[tn * NN + j];
            int   kkn = spb[tn];

            __syncthreads();   // single barrier per t (double buffer covers WAR)
            const float* l1s = l1sh + (t2 & 1) * 48 + 24 * p;
            float u0 = 0.f, u1 = 0.f;
            if (kk == 0) {
                #pragma unroll
                for (int i = 0; i < 24; i += 2) {
                    u0 += l1s[i]     * T0[i];
                    u1 += l1s[i + 1] * T0[i + 1];
                }
            } else if (kk == 1) {
                #pragma unroll
                for (int i = 0; i < 24; i += 2) {
                    u0 += l1s[i]     * T1[i];
                    u1 += l1s[i + 1] * T1[i + 1];
                }
            } else {
                #pragma unroll
                for (int i = 0; i < 24; i += 2) {
                    u0 += l1s[i]     * T2[i];
                    u1 += l1s[i + 1] * T2[i + 1];
                }
            }
            tacc += (u0 + u1) * l2;
            if (p == 0) pacc += yp * l1;

            l1 = l1n; l2 = l2n; yp = ypn; kk = kkn;
        }
        if (c == CH - 1 && p == 0) {   // point-score term for t = T-1
            pacc += ypb[(TT - 1) * NN + j] * ytb[(TT - 1) * NN + j];
        }
        red[tid] = pacc + tacc;
        __syncthreads();
        if (tid == 0) {
            float ssum = 0.f;
            for (int q = 0; q < 96; q++) ssum += red[q];  // fixed order -> deterministic
            g_part[b][c] = ssum;
        }
    }

    // ================= Fused combine: last block to finish does it =================
    __threadfence();                       // publish this block's results
    if (tid == 0) {
        int c = atomicAdd(&g_count, 1);
        s_last = (c == NBLK - 1);
    }
    __syncthreads();
    if (s_last) {
        __threadfence();                   // all other blocks' writes now visible
        if (tid < BB) {
            float q = 0.f;
            #pragma unroll
            for (int c2 = 0; c2 < CH; c2++) q += g_part[tid][c2];  // fixed order
            out[tid] = g_lognorm[tid] - q;
        }
        if (tid == 0) g_count = 0;         // reset for next graph replay
    }
}

extern "C" void kernel_launch(void* const* d_in, const int* in_sizes, int n_in,
                              void* d_out, int out_size)
{
    const float* y_true = (const float*)d_in[0];
    const float* y_pred = (const float*)d_in[1];
    const int*   spkseq = (const int*)d_in[2];
    const float* tr0    = (const float*)d_in[3];
    const float* tr1    = (const float*)d_in[4];
    const float* tr2    = (const float*)d_in[5];

    crf_main<<<NBLK, 96>>>(y_true, y_pred, spkseq, tr0, tr1, tr2, (float*)d_out);
}

// round 12
// speedup vs baseline: 1.0865x; 1.0865x over previous
#include <cuda_runtime.h>

#define BB 64
#define TT 1024
#define NN 48
#define CH 2
#define PF 3   // 1023 steps = 341 * 3 exactly -> no tail guard, branch-free body
#define NBLK (BB + BB * CH)   // 64 chains + 128 scores = 192 blocks

// E layout: two half-row arrays (p = 0 -> rows 0..23, p = 1 -> rows 24..47).
// Each [k][j] half-column = 24 floats padded to stride 28 (= 7 chunks, odd).
// The p=1 array sits 4048 floats after p=0: 4048 f = 1012 chunks == 4 mod 8.
// Phase check (LDS.128, 8 consecutive lanes, tid = 2j + p):
//   chunk-group = (1012 p + 336 k + 7 j + q) mod 8 = (4p + 7j + q) mod 8
//   j = 4w + d, d = 0..3: 7j == 4w - d (mod 8) -> {4w, 4w-1, 4w-2, 4w-3}
//   plus 4p -> the complementary four -> all 8 groups distinct. Conflict-free.
#define EHALF 4032          // 3 * 48 * 28
#define EPOFF 4048          // EHALF + 16-float pad (chunk offset == 4 mod 8)
#define EK    1344          // 48 * 28
#define EJ    28

// Scratch (no cudaMalloc allowed)
__device__ float g_lognorm[BB];
__device__ float g_part[BB][CH];
__device__ int   g_count = 0;   // combine ticket; reset by combiner each call

__global__ __launch_bounds__(96) void crf_main(
    const float* __restrict__ y_true,
    const float* __restrict__ y_pred,
    const int*   __restrict__ spk,
    const float* __restrict__ tr0,
    const float* __restrict__ tr1,
    const float* __restrict__ tr2,
    float* __restrict__ out)
{
    // Chain: E (2 x 4032 + pad) + vsh[2][2][48]. Scores overlay the same buffer.
    __shared__ __align__(16) float sbuf[EPOFF + EHALF + 208];
    __shared__ int s_last;
    const int tid = threadIdx.x;
    const int p = tid & 1;        // i-half: 0 -> rows 0..23, 1 -> rows 24..47
    const int j = tid >> 1;       // output column 0..47

    if (blockIdx.x < BB) {
        // ================= Forward recursion: one block per batch =================
        const int b = blockIdx.x;
        float* vsh = sbuf + EPOFF + EHALF;   // [buf][part][48], 16B-aligned

        // Fill E: element (k, i, j) -> half ph = (i >= 24), local row i - 24*ph.
        for (int idx = tid; idx < 3 * NN * NN; idx += 96) {
            int k  = idx / (NN * NN);
            int rc = idx - k * (NN * NN);
            int i  = rc / NN;
            int cj = rc - i * NN;
            const float* Tk = (k == 0) ? tr0 : (k == 1) ? tr1 : tr2;
            int ph = (i >= 24);
            sbuf[ph * EPOFF + k * EK + cj * EJ + (i - 24 * ph)] = __expf(Tk[rc]);
        }

        const float* ypb = y_pred + b * TT * NN;
        const int*   spb = spk + b * (TT - 1);

        // v_0 = exp(state_0) in A-partials, zeros in B-partials.
        if (tid < 48) {
            vsh[tid]      = __expf(ypb[tid]);
            vsh[48 + tid] = 0.f;
        }

        // Register prefetch ring for emissions + transition selectors.
        float ebuf[PF];
        int   kbuf[PF];
        #pragma unroll
        for (int u = 0; u < PF; u++) {
            ebuf[u] = ypb[(1 + u) * NN + j];
            kbuf[u] = spb[u];
        }
        __syncthreads();

        const float* Epj = sbuf + p * EPOFF + j * EJ;   // per-thread E base (k = 0)

        float m = 0.f;
        float prod = 1.f;                  // lazy renorm-log accumulator
        int cur = 0;
        int t = 1;
        for (int blk = 0; blk < (TT - 1) / PF; blk++) {   // 341 iterations, no tail
            #pragma unroll
            for (int u = 0; u < PF; u++) {
                const int   kk   = kbuf[u];
                const float emit = ebuf[u];
                // Prefetch PF steps ahead (branch-free clamp).
                int tpc  = min(t + PF, TT - 1);
                int sidx = min(t + PF - 1, TT - 2);
                ebuf[u] = ypb[tpc * NN + j];
                kbuf[u] = spb[sidx];

                const float* A  = vsh + cur * 96 + 24 * p;  // this thread's A slice
                const float* Bv = A + 48;                   // matching B slice
                const float* base = vsh + cur * 96;

                // Renorm factor: broadcast scalars + MUFU, parallel with the dot.
                float v00 = base[0] + base[48];
                float pe  = __expf(emit);
                float rp  = __fdividef(pe, v00);

                // E column for this (kk, j, p): 24 contiguous floats, 6x LDS.128,
                // conflict-free by construction.
                const float* Ekj = Epj + kk * EK;

                float a0 = 0.f, a1 = 0.f, a2 = 0.f, a3 = 0.f;
                #pragma unroll
                for (int q = 0; q < 6; q++) {
                    float4 a4 = *(const float4*)(A   + 4 * q);
                    float4 b4 = *(const float4*)(Bv  + 4 * q);
                    float4 e4 = *(const float4*)(Ekj + 4 * q);
                    a0 += (a4.x + b4.x) * e4.x;
                    a1 += (a4.y + b4.y) * e4.y;
                    a2 += (a4.z + b4.z) * e4.z;
                    a3 += (a4.w + b4.w) * e4.w;
                }
                float dot = (a0 + a1) + (a2 + a3);

                // Store this half's partial of the next state (no shfl, no combine).
                vsh[(cur ^ 1) * 96 + p * 48 + j] = dot * rp;
                if (tid == 0) {
                    prod *= v00;                   // lazy: flush log once per blk
                    if (u == PF - 1) { m += __logf(prod); prod = 1.f; }
                }
                __syncthreads();
                cur ^= 1;
                t++;
            }
        }
        if (tid == 0) {
            const float* A = vsh + cur * 96;
            float ssum = 0.f;
            for (int q = 0; q < 48; q++) ssum += A[q] + A[48 + q];  // fixed order
            g_lognorm[b] = m + __logf(ssum);
        }
    } else {
        // ================= Score reductions: (b, chunk) blocks =================
        int idx = blockIdx.x - BB;
        int b   = idx / CH;
        int c   = idx - b * CH;

        float* l1sh = sbuf;        // [2][48] double buffer
        float* red  = sbuf + 96;   // 96-wide reduction scratch

        // Per-thread register copies of raw TRANS: column j, rows 24p..24p+23.
        float T0[24], T1[24], T2[24];
        #pragma unroll
        for (int i = 0; i < 24; i++) {
            int rc = (24 * p + i) * NN + j;
            T0[i] = tr0[rc];
            T1[i] = tr1[rc];
            T2[i] = tr2[rc];
        }

        const float* ytb = y_true + b * TT * NN;
        const float* ypb = y_pred + b * TT * NN;
        const int*   spb = spk + b * (TT - 1);

        const int LEN = (TT - 1 + CH - 1) / CH;   // 512
        int tA  = c * LEN;
        int tBn = tA + LEN; if (tBn > TT - 1) tBn = TT - 1;

        float pacc = 0.f, tacc = 0.f;

        // Software-pipelined loads (one t ahead).
        float l1 = ytb[tA * NN + j];
        float l2 = ytb[(tA + 1) * NN + j];
        float yp = ypb[tA * NN + j];
        int   kk = spb[tA];

        for (int t2 = tA; t2 < tBn; t2++) {
            if (p == 0) l1sh[(t2 & 1) * 48 + j] = l1;

            int tn = min(t2 + 1, tBn - 1);
            float l1n = ytb[tn * NN + j];
            float l2n = ytb[(tn + 1) * NN + j];
            float ypn = ypb[tn * NN + j];
            int   kkn = spb[tn];

            __syncthreads();   // single barrier per t (double buffer covers WAR)
            const float* l1s = l1sh + (t2 & 1) * 48 + 24 * p;
            float u0 = 0.f, u1 = 0.f;
            if (kk == 0) {
                #pragma unroll
                for (int i = 0; i < 24; i += 2) {
                    u0 += l1s[i]     * T0[i];
                    u1 += l1s[i + 1] * T0[i + 1];
                }
            } else if (kk == 1) {
                #pragma unroll
                for (int i = 0; i < 24; i += 2) {
                    u0 += l1s[i]     * T1[i];
                    u1 += l1s[i + 1] * T1[i + 1];
                }
            } else {
                #pragma unroll
                for (int i = 0; i < 24; i += 2) {
                    u0 += l1s[i]     * T2[i];
                    u1 += l1s[i + 1] * T2[i + 1];
                }
            }
            tacc += (u0 + u1) * l2;
            if (p == 0) pacc += yp * l1;

            l1 = l1n; l2 = l2n; yp = ypn; kk = kkn;
        }
        if (c == CH - 1 && p == 0) {   // point-score term for t = T-1
            pacc += ypb[(TT - 1) * NN + j] * ytb[(TT - 1) * NN + j];
        }
        red[tid] = pacc + tacc;
        __syncthreads();
        if (tid == 0) {
            float ssum = 0.f;
            for (int q = 0; q < 96; q++) ssum += red[q];  // fixed order -> deterministic
            g_part[b][c] = ssum;
        }
    }

    // ================= Fused combine: last block to finish does it =================
    __threadfence();                       // publish this block's results
    if (tid == 0) {
        int c = atomicAdd(&g_count, 1);
        s_last = (c == NBLK - 1);
    }
    __syncthreads();
    if (s_last) {
        __threadfence();                   // all other blocks' writes now visible
        if (tid < BB) {
            float q = 0.f;
            #pragma unroll
            for (int c2 = 0; c2 < CH; c2++) q += g_part[tid][c2];  // fixed order
            out[tid] = g_lognorm[tid] - q;
        }
        if (tid == 0) g_count = 0;         // reset for next graph replay
    }
}

extern "C" void kernel_launch(void* const* d_in, const int* in_sizes, int n_in,
                              void* d_out, int out_size)
{
    const float* y_true = (const float*)d_in[0];
    const float* y_pred = (const float*)d_in[1];
    const int*   spkseq = (const int*)d_in[2];
    const float* tr0    = (const float*)d_in[3];
    const float* tr1    = (const float*)d_in[4];
    const float* tr2    = (const float*)d_in[5];

    crf_main<<<NBLK, 96>>>(y_true, y_pred, spkseq, tr0, tr1, tr2, (float*)d_out);
}

// round 14
// speedup vs baseline: 1.2161x; 1.1193x over previous
#include <cuda_runtime.h>

#define BB 64
#define TT 1024
#define NN 48
#define CH 8
#define PF 3   // 1023 steps = 341 * 3 exactly -> no tail guard, branch-free body
#define NBLK (BB + BB * CH)   // 64 chains + 512 scores = 576 blocks (R6 grid)

// Scratch (no cudaMalloc allowed)
__device__ float g_lognorm[BB];
__device__ float g_part[BB][CH];
__device__ int   g_count = 0;   // combine ticket; reset by combiner each call

__global__ __launch_bounds__(96) void crf_main(
    const float* __restrict__ y_true,
    const float* __restrict__ y_pred,
    const int*   __restrict__ spk,
    const float* __restrict__ tr0,
    const float* __restrict__ tr1,
    const float* __restrict__ tr2,
    float* __restrict__ out)
{
    // Chain: Esh (3 x 48 x 48, row stride 50, conflict-free scalar loads)
    // + vsh[2][48] double-buffered combined state. Scores overlay the buffer.
    __shared__ __align__(16) float sbuf[3 * 2400 + 192];
    __shared__ int s_last;
    const int tid = threadIdx.x;
    const int p = tid & 1;        // i-half: 0 -> rows 0..23, 1 -> rows 24..47
    const int j = tid >> 1;       // output column 0..47

    if (blockIdx.x < BB) {
        // ================= Forward recursion: one block per batch =================
        const int b = blockIdx.x;
        float* Esh = sbuf;              // exp(TRANS), k stride 2400, row stride 50
        float* vsh = sbuf + 7200;       // [buf][48]

        for (int idx = tid; idx < 3 * 48 * 48; idx += 96) {
            int k  = idx / 2304;
            int rc = idx - k * 2304;
            int r  = rc / 48;
            int cc = rc - r * 48;
            const float* Tk = (k == 0) ? tr0 : (k == 1) ? tr1 : tr2;
            Esh[k * 2400 + r * 50 + cc] = __expf(Tk[rc]);
        }

        const float* ypb = y_pred + b * TT * NN;
        const int*   spb = spk + b * (TT - 1);

        if (tid < 48) vsh[tid] = __expf(ypb[tid]);   // v_0 = exp(state_0)

        // Register prefetch ring for emissions + transition selectors.
        float ebuf[PF];
        int   kbuf[PF];
        #pragma unroll
        for (int u = 0; u < PF; u++) {
            ebuf[u] = ypb[(1 + u) * NN + j];
            kbuf[u] = spb[u];
        }
        __syncthreads();

        float m = 0.f;
        float prod = 1.f;                  // lazy renorm-log accumulator
        int cur = 0;
        int t = 1;
        for (int blk = 0; blk < (TT - 1) / PF; blk++) {   // 341 iterations, no tail
            #pragma unroll
            for (int u = 0; u < PF; u++) {
                const int   kk   = kbuf[u];
                const float emit = ebuf[u];
                // Prefetch PF steps ahead (branch-free clamp).
                int tpc  = min(t + PF, TT - 1);
                int sidx = min(t + PF - 1, TT - 2);
                ebuf[u] = ypb[tpc * NN + j];
                kbuf[u] = spb[sidx];

                const float* vc = vsh + cur * 48;

                // Renorm factor: broadcast scalar + MUFU, parallel with the dot.
                float v00 = vc[0];
                float pe  = __expf(emit);
                float rp  = __fdividef(pe, v00);

                // Pointer-select transition matrix: no branch.
                // Scalar loads, bank = (16p + 18i + j) mod 32: conflict-free.
                const float* Ekj = Esh + kk * 2400 + (24 * p) * 50 + j;

                // This half's 24-term dot: 6 broadcast float4 v-reads + 24 FMA.
                float a0 = 0.f, a1 = 0.f, a2 = 0.f, a3 = 0.f;
                #pragma unroll
                for (int q = 0; q < 6; q++) {
                    float4 s4 = *(const float4*)(vc + 24 * p + 4 * q);
                    a0 += s4.x * Ekj[(4 * q    ) * 50];
                    a1 += s4.y * Ekj[(4 * q + 1) * 50];
                    a2 += s4.z * Ekj[(4 * q + 2) * 50];
                    a3 += s4.w * Ekj[(4 * q + 3) * 50];
                }
                float dot = (a0 + a1) + (a2 + a3);
                dot += __shfl_xor_sync(0xffffffffu, dot, 1);  // combine i-halves

                if (p == 0) vsh[(cur ^ 1) * 48 + j] = dot * rp;
                if (tid == 0) {
                    prod *= v00;                   // lazy: flush log once per blk
                    if (u == PF - 1) { m += __logf(prod); prod = 1.f; }
                }
                __syncthreads();
                cur ^= 1;
                t++;
            }
        }
        if (tid == 0) {
            const float* vc = vsh + cur * 48;
            float ssum = 0.f;
            for (int q = 0; q < 48; q++) ssum += vc[q];  // fixed order
            g_lognorm[b] = m + __logf(ssum);
        }
    } else {
        // ================= Score reductions: (b, chunk) blocks =================
        int idx = blockIdx.x - BB;
        int b   = idx / CH;
        int c   = idx - b * CH;

        float* l1sh = sbuf;        // [2][48] double buffer
        float* red  = sbuf + 96;   // 96-wide reduction scratch

        // Per-thread register copies of raw TRANS: column j, rows 24p..24p+23.
        float T0[24], T1[24], T2[24];
        #pragma unroll
        for (int i = 0; i < 24; i++) {
            int rc = (24 * p + i) * NN + j;
            T0[i] = tr0[rc];
            T1[i] = tr1[rc];
            T2[i] = tr2[rc];
        }

        const float* ytb = y_true + b * TT * NN;
        const float* ypb = y_pred + b * TT * NN;
        const int*   spb = spk + b * (TT - 1);

        const int LEN = (TT - 1 + CH - 1) / CH;   // 128
        int tA  = c * LEN;
        int tBn = tA + LEN; if (tBn > TT - 1) tBn = TT - 1;

        float pacc = 0.f, tacc = 0.f;

        // Software-pipelined loads (one t ahead).
        float l1 = ytb[tA * NN + j];
        float l2 = ytb[(tA + 1) * NN + j];
        float yp = ypb[tA * NN + j];
        int   kk = spb[tA];

        for (int t2 = tA; t2 < tBn; t2++) {
            if (p == 0) l1sh[(t2 & 1) * 48 + j] = l1;

            int tn = min(t2 + 1, tBn - 1);
            float l1n = ytb[tn * NN + j];
            float l2n = ytb[(tn + 1) * NN + j];
            float ypn = ypb[tn * NN + j];
            int   kkn = spb[tn];

            __syncthreads();   // single barrier per t (double buffer covers WAR)
            const float* l1s = l1sh + (t2 & 1) * 48 + 24 * p;
            float u0 = 0.f, u1 = 0.f;
            if (kk == 0) {
                #pragma unroll
                for (int i = 0; i < 24; i += 2) {
                    u0 += l1s[i]     * T0[i];
                    u1 += l1s[i + 1] * T0[i + 1];
                }
            } else if (kk == 1) {
                #pragma unroll
                for (int i = 0; i < 24; i += 2) {
                    u0 += l1s[i]     * T1[i];
                    u1 += l1s[i + 1] * T1[i + 1];
                }
            } else {
                #pragma unroll
                for (int i = 0; i < 24; i += 2) {
                    u0 += l1s[i]     * T2[i];
                    u1 += l1s[i + 1] * T2[i + 1];
                }
            }
            tacc += (u0 + u1) * l2;
            if (p == 0) pacc += yp * l1;

            l1 = l1n; l2 = l2n; yp = ypn; kk = kkn;
        }
        if (c == CH - 1 && p == 0) {   // point-score term for t = T-1
            pacc += ypb[(TT - 1) * NN + j] * ytb[(TT - 1) * NN + j];
        }
        red[tid] = pacc + tacc;
        __syncthreads();
        if (tid == 0) {
            float ssum = 0.f;
            for (int q = 0; q < 96; q++) ssum += red[q];  // fixed order -> deterministic
            g_part[b][c] = ssum;
        }
    }

    // ================= Fused combine: last block to finish does it =================
    __threadfence();                       // publish this block's results
    if (tid == 0) {
        int c = atomicAdd(&g_count, 1);
        s_last = (c == NBLK - 1);
    }
    __syncthreads();
    if (s_last) {
        __threadfence();                   // all other blocks' writes now visible
        if (tid < BB) {
            float q = 0.f;
            #pragma unroll
            for (int c2 = 0; c2 < CH; c2++) q += g_part[tid][c2];  // fixed order
            out[tid] = g_lognorm[tid] - q;
        }
        if (tid == 0) g_count = 0;         // reset for next graph replay
    }
}

extern "C" void kernel_launch(void* const* d_in, const int* in_sizes, int n_in,
                              void* d_out, int out_size)
{
    const float* y_true = (const float*)d_in[0];
    const float* y_pred = (const float*)d_in[1];
    const int*   spkseq = (const int*)d_in[2];
    const float* tr0    = (const float*)d_in[3];
    const float* tr1    = (const float*)d_in[4];
    const float* tr2    = (const float*)d_in[5];

    crf_main<<<NBLK, 96>>>(y_true, y_pred, spkseq, tr0, tr1, tr2, (float*)d_out);
}